// round 6
// baseline (speedup 1.0000x reference)
#include <cuda_runtime.h>
#include <cuda_bf16.h>
#include <cstdint>
#include <math.h>

#define NN 8192
#define DD 128
#define TILE 128
#define NB (NN / TILE)            // 64
#define NTRI (NB * (NB + 1) / 2)  // 2080
#define NSM 148

#define LDT2 144                  // staged GEMM row stride bytes (64 bf16 + pad)
#define OFF_A 0                   // 128 x 144 = 18432
#define OFF_B 18432
#define OFF_D0 36864              // dist buf 0: 64 KB (swizzled 128x128 fp32)
#define OFF_D1 102400             // dist buf 1
#define OFF_RING 167936           // 5 x 8192
#define CHUNK_BYTES 8192
#define OFF_NI 208896             // 128 floats
#define OFF_NJ 209408             // 128 floats
#define OFF_RED 209920            // 3 x 8 floats
#define SMEM_DYN 210048

__device__ double g_sumDW;
__device__ double g_sumW;
__device__ int    g_maxSq;
__device__ float  g_norms[NN];
__device__ __nv_bfloat16 g_ehi[NN * DD];
__device__ __nv_bfloat16 g_elo[NN * DD];

// ---------------- helpers ----------------
__device__ __forceinline__ uint32_t smem_u32(const void* p) {
    uint32_t a;
    asm("{ .reg .u64 t; cvta.to.shared.u64 t, %1; cvt.u32.u64 %0, t; }"
        : "=r"(a) : "l"(p));
    return a;
}
__device__ __forceinline__ void ldsm_x4(uint32_t& r0, uint32_t& r1,
                                        uint32_t& r2, uint32_t& r3, uint32_t a) {
    asm volatile("ldmatrix.sync.aligned.m8n8.x4.shared.b16 {%0,%1,%2,%3}, [%4];"
                 : "=r"(r0), "=r"(r1), "=r"(r2), "=r"(r3) : "r"(a));
}
__device__ __forceinline__ void mma16816(float* d, const uint32_t* a,
                                         const uint32_t* b) {
    asm volatile(
        "mma.sync.aligned.m16n8k16.row.col.f32.bf16.bf16.f32 "
        "{%0,%1,%2,%3}, {%4,%5,%6,%7}, {%8,%9}, {%0,%1,%2,%3};"
        : "+f"(d[0]), "+f"(d[1]), "+f"(d[2]), "+f"(d[3])
        : "r"(a[0]), "r"(a[1]), "r"(a[2]), "r"(a[3]), "r"(b[0]), "r"(b[1]));
}
__device__ __forceinline__ void cp16(uint32_t dst, const void* src) {
    asm volatile("cp.async.cg.shared.global [%0], [%1], 16;"
                 :: "r"(dst), "l"(src) : "memory");
}
#define CP_COMMIT() asm volatile("cp.async.commit_group;" ::: "memory")
#define CP_WAIT3()  asm volatile("cp.async.wait_group 3;" ::: "memory")
#define BAR_P()     asm volatile("bar.sync 1, 256;" ::: "memory")
#define BAR_C()     asm volatile("bar.sync 2, 256;" ::: "memory")

// XOR-swizzled dist word index: conflict-free row AND column access
__device__ __forceinline__ uint32_t dword(int r, int c) {
    return (uint32_t)(((r >> 5) * 4 + (c >> 5)) * 1024
                      + (r & 31) * 32 + ((c & 31) ^ (r & 31)));
}
__device__ __forceinline__ void tri_decode(int t, int& bi, int& bj) {
#define SFUN(b) ((b) * NB - (b) * ((b) - 1) / 2)
    float ff = 2.0f * NB + 1.0f;
    int b = (int)((ff - sqrtf(ff * ff - 8.0f * (float)t)) * 0.5f);
    if (b < 0) b = 0;
    if (b > NB - 1) b = NB - 1;
    while (b > 0 && SFUN(b) > t) b--;
    while (SFUN(b + 1) <= t) b++;
    bi = b;
    bj = b + (t - SFUN(b));
}

// ---------------- prep kernels ----------------
__global__ void init_kernel() {
    g_sumDW = 0.0;
    g_sumW  = 0.0;
    g_maxSq = 0;
}

__global__ __launch_bounds__(256) void convert_kernel(const float* __restrict__ emb) {
    int idx = blockIdx.x * 256 + threadIdx.x;
    float x = emb[idx];
    __nv_bfloat16 hi = __float2bfloat16(x);
    g_ehi[idx] = hi;
    g_elo[idx] = __float2bfloat16(x - __bfloat162float(hi));
}

__global__ __launch_bounds__(256) void norm_kernel(const float* __restrict__ emb) {
    int row = blockIdx.x * 256 + threadIdx.x;
    const float4* p = reinterpret_cast<const float4*>(emb) + (size_t)row * (DD / 4);
    float s = 0.f;
#pragma unroll
    for (int i = 0; i < DD / 4; i++) {
        float4 v = p[i];
        s += v.x * v.x + v.y * v.y + v.z * v.z + v.w * v.w;
    }
    g_norms[row] = s;
}

// ---------------- main: persistent, warp-specialized ----------------
__global__ __launch_bounds__(512, 1) void main_kernel(const float* __restrict__ W) {
    extern __shared__ char sm[];
    const uint32_t smbase = smem_u32(sm);
    const int tid = threadIdx.x;
    const int wid = tid >> 5;
    const int lane = tid & 31;
    const int bid = blockIdx.x;

    const int ntiles = (NTRI - bid - 1) / NSM + 1;   // tiles: bid + NSM*k

    float* nI = (float*)(sm + OFF_NI);
    float* nJ = (float*)(sm + OFF_NJ);
    float* redDW = (float*)(sm + OFF_RED);
    float* redW  = (float*)(sm + OFF_RED + 32);
    float* redM  = (float*)(sm + OFF_RED + 64);

    // producer state
    float maxsq = 0.f;
    const uint32_t a_row = (lane & 15);
    const uint32_t a_koff = ((lane >> 4) << 3) * 2;
    const uint32_t b_row = (lane & 7) + ((lane >> 4) << 3);
    const uint32_t b_koff = (((lane >> 3) & 1) << 3) * 2;
    const int wm = wid & 3;
    const int wn = (wid >> 2) & 1;

    // consumer state
    float sDW = 0.f, sW = 0.f;
    const int ctid = tid & 255;
    const int cw = wid - 8;
    int is_k = 0, is_q = 0;            // issue pointer (tile idx, chunk idx)
    int is_gi0 = 0, is_gj0 = 0, is_nch = 0;
    int qi = 0, qc = 0;                // global issued / consumed chunk counters
    if (tid >= 256 && ntiles > 0) {
        int bi, bj;
        tri_decode(bid, bi, bj);
        is_gi0 = bi * TILE; is_gj0 = bj * TILE;
        is_nch = (bi == bj) ? 8 : 16;
    }

    // issue one W chunk (or empty commit if stream exhausted)
    auto issue_one = [&]() {
        if (is_k < ntiles) {
            int q = is_q;
            int srcR = ((q >= 8) ? is_gj0 : is_gi0) + (q & 7) * 16;
            int colB = (q >= 8) ? is_gi0 : is_gj0;
            int jr = ctid >> 4, c16 = ctid & 15;
            const char* src = (const char*)W + ((size_t)(srcR + jr) * NN + colB) * 4;
            uint32_t dst = smbase + OFF_RING + (qi % 5) * CHUNK_BYTES + jr * 512;
            cp16(dst + c16 * 16, src + (size_t)c16 * 16);
            cp16(dst + (c16 + 16) * 16, src + (size_t)(c16 + 16) * 16);
            qi++;
            if (++is_q == is_nch) {
                is_q = 0;
                if (++is_k < ntiles) {
                    int bi, bj;
                    tri_decode(bid + NSM * is_k, bi, bj);
                    is_gi0 = bi * TILE; is_gj0 = bj * TILE;
                    is_nch = (bi == bj) ? 8 : 16;
                }
            }
        }
        CP_COMMIT();
    };

    for (int k = 0; k <= ntiles; k++) {
        if (tid < 256) {
            // ================= PRODUCER: GEMM + dist for tile k =================
            if (k < ntiles) {
                int bi, bj;
                tri_decode(bid + NSM * k, bi, bj);
                const int gi0 = bi * TILE, gj0 = bj * TILE;
                if (tid < 128) nI[tid] = g_norms[gi0 + tid];
                else           nJ[tid - 128] = g_norms[gj0 + tid - 128];

                float acc[2][8][4];
#pragma unroll
                for (int mi = 0; mi < 2; mi++)
#pragma unroll
                    for (int ni = 0; ni < 8; ni++)
#pragma unroll
                        for (int q = 0; q < 4; q++) acc[mi][ni][q] = 0.f;

#pragma unroll
                for (int s = 0; s < 4; s++) {
                    const uint4* src = (const uint4*)((s < 2) ? g_ehi : g_elo);
                    const int kh = (s & 1) * 8;
                    BAR_P();           // prev stage fully consumed
#pragma unroll
                    for (int it = 0; it < 4; it++) {
                        int idx = it * 256 + tid;
                        int r = idx >> 3, c = idx & 7;
                        *(uint4*)(sm + OFF_A + r * LDT2 + c * 16) =
                            src[(size_t)(gi0 + r) * 16 + kh + c];
                        *(uint4*)(sm + OFF_B + r * LDT2 + c * 16) =
                            src[(size_t)(gj0 + r) * 16 + kh + c];
                    }
                    BAR_P();
#pragma unroll
                    for (int ks = 0; ks < 4; ks++) {
                        const uint32_t k0b = ks * 32;
                        uint32_t af[2][4];
#pragma unroll
                        for (int mi = 0; mi < 2; mi++) {
                            uint32_t addr = smbase + OFF_A +
                                (wm * 32 + mi * 16 + a_row) * LDT2 + k0b + a_koff;
                            ldsm_x4(af[mi][0], af[mi][1], af[mi][2], af[mi][3], addr);
                        }
                        uint32_t bf[8][2];
#pragma unroll
                        for (int nq = 0; nq < 4; nq++) {
                            uint32_t addr = smbase + OFF_B +
                                (wn * 64 + nq * 16 + b_row) * LDT2 + k0b + b_koff;
                            uint32_t r0, r1, r2, r3;
                            ldsm_x4(r0, r1, r2, r3, addr);
                            bf[nq * 2][0] = r0; bf[nq * 2][1] = r1;
                            bf[nq * 2 + 1][0] = r2; bf[nq * 2 + 1][1] = r3;
                        }
#pragma unroll
                        for (int mi = 0; mi < 2; mi++)
#pragma unroll
                            for (int ni = 0; ni < 8; ni++)
                                mma16816(acc[mi][ni], af[mi], bf[ni]);
                    }
                }
                BAR_P();               // nI/nJ + last LDSM done

                float* dist = (float*)(sm + OFF_D0 + (k & 1) * 65536);
                const int crow = lane >> 2;
                const int ccol = (lane & 3) * 2;
#pragma unroll
                for (int mi = 0; mi < 2; mi++) {
#pragma unroll
                    for (int ni = 0; ni < 8; ni++) {
#pragma unroll
                        for (int h = 0; h < 2; h++) {
                            int r = wm * 32 + mi * 16 + crow + h * 8;
                            int c = wn * 64 + ni * 8 + ccol;
                            float nn_ = nI[r];
                            float s0 = fmaxf(nn_ + nJ[c]     - 2.f * acc[mi][ni][2 * h],     0.f);
                            float s1 = fmaxf(nn_ + nJ[c + 1] - 2.f * acc[mi][ni][2 * h + 1], 0.f);
                            maxsq = fmaxf(maxsq, fmaxf(s0, s1));
                            dist[dword(r, c)]     = sqrtf(s0);
                            dist[dword(r, c + 1)] = sqrtf(s1);
                        }
                    }
                }
            }
        } else {
            // ================= CONSUMER: W stream for tile k-1 =================
            if (k == 0) {
                issue_one(); issue_one(); issue_one(); issue_one();  // 4 in flight
            } else {
                int bi, bj;
                tri_decode(bid + NSM * (k - 1), bi, bj);
                const int nch = (bi == bj) ? 8 : 16;
                const float* dist = (const float*)(sm + OFF_D0 + ((k - 1) & 1) * 65536);
                const int jr0 = cw * 2;
                for (int q = 0; q < nch; q++) {
                    CP_WAIT3();
                    BAR_C();           // chunk (qc) landed for all consumer threads
                    const float* stg =
                        (const float*)(sm + OFF_RING + (qc % 5) * CHUNK_BYTES);
                    qc++;
                    if (q < 8) {
#pragma unroll
                        for (int rr = 0; rr < 2; rr++) {
                            int jr = jr0 + rr;
                            int r = q * 16 + jr;
#pragma unroll
                            for (int u = 0; u < 4; u++) {
                                int c = lane + 32 * u;
                                float w = stg[jr * 128 + c];
                                sDW += dist[dword(r, c)] * w;
                                sW += w;
                            }
                        }
                    } else {
#pragma unroll
                        for (int rr = 0; rr < 2; rr++) {
                            int jr = jr0 + rr;
                            int jl = (q - 8) * 16 + jr;
#pragma unroll
                            for (int u = 0; u < 4; u++) {
                                int c = lane + 32 * u;
                                float w = stg[jr * 128 + c];
                                sDW += dist[dword(c, jl)] * w;
                                sW += w;
                            }
                        }
                    }
                    BAR_C();           // all reads of slot done before refill
                    issue_one();
                }
            }
        }
        __syncthreads();               // buffer handoff
    }

    // ---------------- final reductions ----------------
#pragma unroll
    for (int o = 16; o > 0; o >>= 1) {
        sDW += __shfl_xor_sync(0xFFFFFFFF, sDW, o);
        sW  += __shfl_xor_sync(0xFFFFFFFF, sW, o);
        maxsq = fmaxf(maxsq, __shfl_xor_sync(0xFFFFFFFF, maxsq, o));
    }
    if (lane == 0) {
        if (wid < 8) redM[wid] = maxsq;
        else { redDW[wid - 8] = sDW; redW[wid - 8] = sW; }
    }
    __syncthreads();
    if (tid == 0) {
        double a = 0.0, b = 0.0;
        float m = 0.f;
#pragma unroll
        for (int w = 0; w < 8; w++) {
            a += (double)redDW[w];
            b += (double)redW[w];
            m = fmaxf(m, redM[w]);
        }
        atomicAdd(&g_sumDW, a);
        atomicAdd(&g_sumW, b);
        atomicMax(&g_maxSq, __float_as_int(m));
    }
}

// ---------------- finalize ----------------
__global__ void finalize_kernel(float* out) {
    double maxd = sqrt((double)__int_as_float(g_maxSq));
    double res = (g_sumW - g_sumDW / maxd) / ((double)NN * (double)NN);
    out[0] = (float)res;
}

extern "C" void kernel_launch(void* const* d_in, const int* in_sizes, int n_in,
                              void* d_out, int out_size) {
    const float* emb = (const float*)d_in[0];   // [8192, 128] fp32
    const float* W   = (const float*)d_in[1];   // [8192, 8192] fp32
    float* out = (float*)d_out;

    cudaFuncSetAttribute(main_kernel, cudaFuncAttributeMaxDynamicSharedMemorySize,
                         SMEM_DYN);

    init_kernel<<<1, 1>>>();
    convert_kernel<<<(NN * DD) / 256, 256>>>(emb);
    norm_kernel<<<NN / 256, 256>>>(emb);
    main_kernel<<<NSM, 512, SMEM_DYN>>>(W);
    finalize_kernel<<<1, 1>>>(out);
}

// round 7
// speedup vs baseline: 1.1004x; 1.1004x over previous
#include <cuda_runtime.h>
#include <cuda_bf16.h>
#include <cstdint>
#include <math.h>

#define NN 8192
#define DD 128
#define TILE 128
#define NB (NN / TILE)           // 64

#define LDT 272                  // GEMM smem row stride (bytes)
#define TILE_BYTES (TILE * LDT)  // 34816
#define OFF_A 0
#define OFF_B TILE_BYTES
#define SMEM_DYN (2 * TILE_BYTES)  // 69632 -> 2 CTAs/SM

__device__ double g_sumDW;
__device__ double g_sumW;
__device__ int    g_maxSq;       // float bits; all >= 0 so int-max works
__device__ float  g_norms[NN];
__device__ __nv_bfloat16 g_ehi[NN * DD];
__device__ __nv_bfloat16 g_elo[NN * DD];

// ---------------- helpers ----------------
__device__ __forceinline__ uint32_t smem_u32(const void* p) {
    uint32_t a;
    asm("{ .reg .u64 t; cvta.to.shared.u64 t, %1; cvt.u32.u64 %0, t; }"
        : "=r"(a) : "l"(p));
    return a;
}
__device__ __forceinline__ void ldsm_x4(uint32_t& r0, uint32_t& r1,
                                        uint32_t& r2, uint32_t& r3, uint32_t a) {
    asm volatile("ldmatrix.sync.aligned.m8n8.x4.shared.b16 {%0,%1,%2,%3}, [%4];"
                 : "=r"(r0), "=r"(r1), "=r"(r2), "=r"(r3) : "r"(a));
}
__device__ __forceinline__ void mma16816(float* d, const uint32_t* a,
                                         const uint32_t* b) {
    asm volatile(
        "mma.sync.aligned.m16n8k16.row.col.f32.bf16.bf16.f32 "
        "{%0,%1,%2,%3}, {%4,%5,%6,%7}, {%8,%9}, {%0,%1,%2,%3};"
        : "+f"(d[0]), "+f"(d[1]), "+f"(d[2]), "+f"(d[3])
        : "r"(a[0]), "r"(a[1]), "r"(a[2]), "r"(a[3]), "r"(b[0]), "r"(b[1]));
}
__device__ __forceinline__ float fsqrt_approx(float x) {
    float r;
    asm("sqrt.approx.f32 %0, %1;" : "=f"(r) : "f"(x));
    return r;
}

// ---------------- prep kernels ----------------
__global__ void init_kernel() {
    g_sumDW = 0.0;
    g_sumW  = 0.0;
    g_maxSq = 0;
}

__global__ __launch_bounds__(256) void convert_kernel(const float* __restrict__ emb) {
    int idx = blockIdx.x * 256 + threadIdx.x;
    float x = emb[idx];
    __nv_bfloat16 hi = __float2bfloat16(x);
    g_ehi[idx] = hi;
    g_elo[idx] = __float2bfloat16(x - __bfloat162float(hi));
}

__global__ __launch_bounds__(256) void norm_kernel(const float* __restrict__ emb) {
    int row = blockIdx.x * 256 + threadIdx.x;
    const float4* p = reinterpret_cast<const float4*>(emb) + (size_t)row * (DD / 4);
    float s = 0.f;
#pragma unroll
    for (int i = 0; i < DD / 4; i++) {
        float4 v = p[i];
        s += v.x * v.x + v.y * v.y + v.z * v.z + v.w * v.w;
    }
    g_norms[row] = s;
}

// ---------------- main kernel: full grid, register epilogue ----------------
__global__ __launch_bounds__(256, 2) void main_kernel(const float* __restrict__ W) {
    extern __shared__ char sm[];
    __shared__ float nI[TILE];
    __shared__ float nJ[TILE];
    __shared__ float redDW[8], redW[8], redM[8];

    const int tid = threadIdx.x;
    const int wid = tid >> 5;
    const int lane = tid & 31;
    const int gi0 = blockIdx.y * TILE;
    const int gj0 = blockIdx.x * TILE;

    if (tid < TILE) nI[tid] = g_norms[gi0 + tid];
    else            nJ[tid - TILE] = g_norms[gj0 + tid - TILE];

    // ---- GEMM: K=256 as two 128-chunks (hi then lo); 8 warps, 32x64 each ----
    const int wm = wid & 3;
    const int wn = wid >> 2;
    float acc[2][8][4];
#pragma unroll
    for (int mi = 0; mi < 2; mi++)
#pragma unroll
        for (int ni = 0; ni < 8; ni++)
#pragma unroll
            for (int q = 0; q < 4; q++) acc[mi][ni][q] = 0.f;

    const uint32_t smA = smem_u32(sm) + OFF_A;
    const uint32_t smB = smem_u32(sm) + OFF_B;
    const uint32_t a_row = (lane & 15);
    const uint32_t a_koff = ((lane >> 4) << 3) * 2;
    const uint32_t b_row = (lane & 7) + ((lane >> 4) << 3);
    const uint32_t b_koff = (((lane >> 3) & 1) << 3) * 2;

    for (int kc = 0; kc < 2; kc++) {
        const uint4* src = (const uint4*)(kc ? g_elo : g_ehi);
        if (kc) __syncthreads();       // previous chunk fully consumed
#pragma unroll
        for (int it = 0; it < 8; it++) {
            int idx = it * 256 + tid;
            int r = idx >> 4, c = idx & 15;
            *(uint4*)(sm + OFF_A + r * LDT + c * 16) = src[(size_t)(gi0 + r) * 16 + c];
            *(uint4*)(sm + OFF_B + r * LDT + c * 16) = src[(size_t)(gj0 + r) * 16 + c];
        }
        __syncthreads();

#pragma unroll
        for (int ks = 0; ks < 8; ks++) {
            const uint32_t k0b = ks * 32;
            uint32_t af[2][4];
#pragma unroll
            for (int mi = 0; mi < 2; mi++) {
                uint32_t addr = smA + (wm * 32 + mi * 16 + a_row) * LDT + k0b + a_koff;
                ldsm_x4(af[mi][0], af[mi][1], af[mi][2], af[mi][3], addr);
            }
            uint32_t bf[8][2];
#pragma unroll
            for (int nq = 0; nq < 4; nq++) {
                uint32_t addr = smB + (wn * 64 + nq * 16 + b_row) * LDT + k0b + b_koff;
                uint32_t r0, r1, r2, r3;
                ldsm_x4(r0, r1, r2, r3, addr);
                bf[nq * 2][0] = r0; bf[nq * 2][1] = r1;
                bf[nq * 2 + 1][0] = r2; bf[nq * 2 + 1][1] = r3;
            }
#pragma unroll
            for (int mi = 0; mi < 2; mi++)
#pragma unroll
                for (int ni = 0; ni < 8; ni++)
                    mma16816(acc[mi][ni], af[mi], bf[ni]);
        }
    }

    // ---- register epilogue: dist from acc, W gathered at fragment coords ----
    const int crow = lane >> 2;
    const int ccol = (lane & 3) * 2;
    float sDW = 0.f, sW = 0.f, maxsq = 0.f;

#pragma unroll
    for (int mi = 0; mi < 2; mi++) {
#pragma unroll
        for (int h = 0; h < 2; h++) {
            const int r = wm * 32 + mi * 16 + crow + h * 8;
            const float* wrow = W + (size_t)(gi0 + r) * NN + gj0 + wn * 64 + ccol;
            float2 wv[8];
#pragma unroll
            for (int ni = 0; ni < 8; ni++)
                wv[ni] = *(const float2*)(wrow + ni * 8);   // MLP-8 batch

            const float nival = nI[r];
#pragma unroll
            for (int ni = 0; ni < 8; ni++) {
                float2 nj = *(const float2*)(&nJ[wn * 64 + ni * 8 + ccol]);
                float s0 = fmaxf(nival + nj.x - 2.f * acc[mi][ni][2 * h],     0.f);
                float s1 = fmaxf(nival + nj.y - 2.f * acc[mi][ni][2 * h + 1], 0.f);
                maxsq = fmaxf(maxsq, fmaxf(s0, s1));
                sDW += fsqrt_approx(s0) * wv[ni].x + fsqrt_approx(s1) * wv[ni].y;
                sW  += wv[ni].x + wv[ni].y;
            }
        }
    }

    // ---- reductions ----
#pragma unroll
    for (int o = 16; o > 0; o >>= 1) {
        sDW += __shfl_xor_sync(0xFFFFFFFF, sDW, o);
        sW  += __shfl_xor_sync(0xFFFFFFFF, sW, o);
        maxsq = fmaxf(maxsq, __shfl_xor_sync(0xFFFFFFFF, maxsq, o));
    }
    if (lane == 0) { redDW[wid] = sDW; redW[wid] = sW; redM[wid] = maxsq; }
    __syncthreads();
    if (tid == 0) {
        double a = 0.0, b = 0.0;
        float m = 0.f;
#pragma unroll
        for (int w = 0; w < 8; w++) {
            a += (double)redDW[w];
            b += (double)redW[w];
            m = fmaxf(m, redM[w]);
        }
        atomicAdd(&g_sumDW, a);
        atomicAdd(&g_sumW, b);
        atomicMax(&g_maxSq, __float_as_int(m));
    }
}

// ---------------- finalize ----------------
__global__ void finalize_kernel(float* out) {
    double maxd = sqrt((double)__int_as_float(g_maxSq));
    double res = (g_sumW - g_sumDW / maxd) / ((double)NN * (double)NN);
    out[0] = (float)res;
}

extern "C" void kernel_launch(void* const* d_in, const int* in_sizes, int n_in,
                              void* d_out, int out_size) {
    const float* emb = (const float*)d_in[0];   // [8192, 128] fp32
    const float* W   = (const float*)d_in[1];   // [8192, 8192] fp32
    float* out = (float*)d_out;

    cudaFuncSetAttribute(main_kernel, cudaFuncAttributeMaxDynamicSharedMemorySize,
                         SMEM_DYN);

    init_kernel<<<1, 1>>>();
    convert_kernel<<<(NN * DD) / 256, 256>>>(emb);
    norm_kernel<<<NN / 256, 256>>>(emb);
    dim3 grid(NB, NB);   // full 64x64 grid of ordered blocks
    main_kernel<<<grid, 256, SMEM_DYN>>>(W);
    finalize_kernel<<<1, 1>>>(out);
}

// round 8
// speedup vs baseline: 1.4161x; 1.2869x over previous
#include <cuda_runtime.h>
#include <cuda_bf16.h>
#include <cstdint>
#include <math.h>

#define NN 8192
#define DD 128
#define TILE 128
#define NB (NN / TILE)            // 64
#define NTRI (NB * (NB + 1) / 2)  // 2080 triangular tiles

#define LDT 272                   // GEMM smem row stride (bytes)
#define TILE_BYTES (TILE * LDT)   // 34816
#define OFF_A 0
#define OFF_B TILE_BYTES
#define SMEM_DYN (2 * TILE_BYTES) // 69632 -> 2 CTAs/SM

__device__ double g_sumDW;
__device__ double g_sumW;
__device__ int    g_maxSq;        // float bits; all >= 0 so int-max works
__device__ float  g_norms[NN];
__device__ __nv_bfloat16 g_ehi[NN * DD];
__device__ __nv_bfloat16 g_elo[NN * DD];

// ---------------- helpers ----------------
__device__ __forceinline__ uint32_t smem_u32(const void* p) {
    uint32_t a;
    asm("{ .reg .u64 t; cvta.to.shared.u64 t, %1; cvt.u32.u64 %0, t; }"
        : "=r"(a) : "l"(p));
    return a;
}
__device__ __forceinline__ void ldsm_x4(uint32_t& r0, uint32_t& r1,
                                        uint32_t& r2, uint32_t& r3, uint32_t a) {
    asm volatile("ldmatrix.sync.aligned.m8n8.x4.shared.b16 {%0,%1,%2,%3}, [%4];"
                 : "=r"(r0), "=r"(r1), "=r"(r2), "=r"(r3) : "r"(a));
}
__device__ __forceinline__ void mma16816(float* d, const uint32_t* a,
                                         const uint32_t* b) {
    asm volatile(
        "mma.sync.aligned.m16n8k16.row.col.f32.bf16.bf16.f32 "
        "{%0,%1,%2,%3}, {%4,%5,%6,%7}, {%8,%9}, {%0,%1,%2,%3};"
        : "+f"(d[0]), "+f"(d[1]), "+f"(d[2]), "+f"(d[3])
        : "r"(a[0]), "r"(a[1]), "r"(a[2]), "r"(a[3]), "r"(b[0]), "r"(b[1]));
}
__device__ __forceinline__ float fsqrt_approx(float x) {
    float r;
    asm("sqrt.approx.f32 %0, %1;" : "=f"(r) : "f"(x));
    return r;
}

// ---------------- prep kernels ----------------
__global__ void init_kernel() {
    g_sumDW = 0.0;
    g_sumW  = 0.0;
    g_maxSq = 0;
}

__global__ __launch_bounds__(256) void convert_kernel(const float* __restrict__ emb) {
    int idx = blockIdx.x * 256 + threadIdx.x;
    float x = emb[idx];
    __nv_bfloat16 hi = __float2bfloat16(x);
    g_ehi[idx] = hi;
    g_elo[idx] = __float2bfloat16(x - __bfloat162float(hi));
}

__global__ __launch_bounds__(256) void norm_kernel(const float* __restrict__ emb) {
    int row = blockIdx.x * 256 + threadIdx.x;
    const float4* p = reinterpret_cast<const float4*>(emb) + (size_t)row * (DD / 4);
    float s = 0.f;
#pragma unroll
    for (int i = 0; i < DD / 4; i++) {
        float4 v = p[i];
        s += v.x * v.x + v.y * v.y + v.z * v.z + v.w * v.w;
    }
    g_norms[row] = s;
}

// ---------------- main: triangular grid, register epilogue ----------------
__global__ __launch_bounds__(256, 2) void main_kernel(const float* __restrict__ W) {
    extern __shared__ char sm[];
    __shared__ float nI[TILE];
    __shared__ float nJ[TILE];
    __shared__ float redDW[8], redW[8], redM[8];

    const int tid = threadIdx.x;
    const int wid = tid >> 5;
    const int lane = tid & 31;

    // ---- triangular tile decode: bi <= bj ----
    int t = blockIdx.x;
    float ff = 2.0f * NB + 1.0f;
    int bi = (int)((ff - sqrtf(ff * ff - 8.0f * (float)t)) * 0.5f);
    if (bi < 0) bi = 0;
    if (bi > NB - 1) bi = NB - 1;
#define SFUN(b) ((b) * NB - (b) * ((b) - 1) / 2)
    while (bi > 0 && SFUN(bi) > t) bi--;
    while (SFUN(bi + 1) <= t) bi++;
    const int bj = bi + (t - SFUN(bi));
    const int gi0 = bi * TILE;
    const int gj0 = bj * TILE;
    const bool diag = (bi == bj);

    if (tid < TILE) nI[tid] = g_norms[gi0 + tid];
    else            nJ[tid - TILE] = g_norms[gj0 + tid - TILE];

    // ---- GEMM: K=256 as two 128-chunks (hi then lo); 8 warps, 32x64 each ----
    const int wm = wid & 3;
    const int wn = wid >> 2;
    float acc[2][8][4];
#pragma unroll
    for (int mi = 0; mi < 2; mi++)
#pragma unroll
        for (int ni = 0; ni < 8; ni++)
#pragma unroll
            for (int q = 0; q < 4; q++) acc[mi][ni][q] = 0.f;

    const uint32_t smA = smem_u32(sm) + OFF_A;
    const uint32_t smB = smem_u32(sm) + OFF_B;
    const uint32_t a_row = (lane & 15);
    const uint32_t a_koff = ((lane >> 4) << 3) * 2;
    const uint32_t b_row = (lane & 7) + ((lane >> 4) << 3);
    const uint32_t b_koff = (((lane >> 3) & 1) << 3) * 2;

    for (int kc = 0; kc < 2; kc++) {
        const uint4* src = (const uint4*)(kc ? g_elo : g_ehi);
        if (kc) __syncthreads();       // previous chunk fully consumed
#pragma unroll
        for (int it = 0; it < 8; it++) {
            int idx = it * 256 + tid;
            int r = idx >> 4, c = idx & 15;
            *(uint4*)(sm + OFF_A + r * LDT + c * 16) = src[(size_t)(gi0 + r) * 16 + c];
            *(uint4*)(sm + OFF_B + r * LDT + c * 16) = src[(size_t)(gj0 + r) * 16 + c];
        }
        __syncthreads();

#pragma unroll
        for (int ks = 0; ks < 8; ks++) {
            const uint32_t k0b = ks * 32;
            uint32_t af[2][4];
#pragma unroll
            for (int mi = 0; mi < 2; mi++) {
                uint32_t addr = smA + (wm * 32 + mi * 16 + a_row) * LDT + k0b + a_koff;
                ldsm_x4(af[mi][0], af[mi][1], af[mi][2], af[mi][3], addr);
            }
            uint32_t bf[8][2];
#pragma unroll
            for (int nq = 0; nq < 4; nq++) {
                uint32_t addr = smB + (wn * 64 + nq * 16 + b_row) * LDT + k0b + b_koff;
                uint32_t r0, r1, r2, r3;
                ldsm_x4(r0, r1, r2, r3, addr);
                bf[nq * 2][0] = r0; bf[nq * 2][1] = r1;
                bf[nq * 2 + 1][0] = r2; bf[nq * 2 + 1][1] = r3;
            }
#pragma unroll
            for (int mi = 0; mi < 2; mi++)
#pragma unroll
                for (int ni = 0; ni < 8; ni++)
                    mma16816(acc[mi][ni], af[mi], bf[ni]);
        }
    }

    // ---- register epilogue: dist from acc, W gathered at fragment coords ----
    const int crow = lane >> 2;
    const int ccol = (lane & 3) * 2;
    float sDW = 0.f, sW = 0.f, maxsq = 0.f;

#pragma unroll
    for (int mi = 0; mi < 2; mi++) {
#pragma unroll
        for (int h = 0; h < 2; h++) {
            const int r = wm * 32 + mi * 16 + crow + h * 8;
            const int cbase = wn * 64 + ccol;
            const float* w1row = W + (size_t)(gi0 + r) * NN + gj0 + cbase;
            float2 wv[8];
#pragma unroll
            for (int ni = 0; ni < 8; ni++)
                wv[ni] = *(const float2*)(w1row + ni * 8);     // row-order, MLP-8

            float w2a[8], w2b[8];
            if (!diag) {
                const float* w2col = W + (size_t)gj0 * NN + gi0 + r;
#pragma unroll
                for (int ni = 0; ni < 8; ni++) {               // transposed gather
                    w2a[ni] = w2col[(size_t)(cbase + ni * 8) * NN];
                    w2b[ni] = w2col[(size_t)(cbase + ni * 8 + 1) * NN];
                }
            }

            const float nival = nI[r];
#pragma unroll
            for (int ni = 0; ni < 8; ni++) {
                float2 nj = *(const float2*)(&nJ[cbase + ni * 8]);
                float s0 = fmaxf(nival + nj.x - 2.f * acc[mi][ni][2 * h],     0.f);
                float s1 = fmaxf(nival + nj.y - 2.f * acc[mi][ni][2 * h + 1], 0.f);
                maxsq = fmaxf(maxsq, fmaxf(s0, s1));
                float d0 = fsqrt_approx(s0);
                float d1 = fsqrt_approx(s1);
                if (diag) {
                    sDW += d0 * wv[ni].x + d1 * wv[ni].y;
                    sW  += wv[ni].x + wv[ni].y;
                } else {
                    sDW += d0 * (wv[ni].x + w2a[ni]) + d1 * (wv[ni].y + w2b[ni]);
                    sW  += (wv[ni].x + w2a[ni]) + (wv[ni].y + w2b[ni]);
                }
            }
        }
    }

    // ---- reductions ----
#pragma unroll
    for (int o = 16; o > 0; o >>= 1) {
        sDW += __shfl_xor_sync(0xFFFFFFFF, sDW, o);
        sW  += __shfl_xor_sync(0xFFFFFFFF, sW, o);
        maxsq = fmaxf(maxsq, __shfl_xor_sync(0xFFFFFFFF, maxsq, o));
    }
    if (lane == 0) { redDW[wid] = sDW; redW[wid] = sW; redM[wid] = maxsq; }
    __syncthreads();
    if (tid == 0) {
        double a = 0.0, b = 0.0;
        float m = 0.f;
#pragma unroll
        for (int w = 0; w < 8; w++) {
            a += (double)redDW[w];
            b += (double)redW[w];
            m = fmaxf(m, redM[w]);
        }
        atomicAdd(&g_sumDW, a);
        atomicAdd(&g_sumW, b);
        atomicMax(&g_maxSq, __float_as_int(m));
    }
}

// ---------------- finalize ----------------
__global__ void finalize_kernel(float* out) {
    double maxd = sqrt((double)__int_as_float(g_maxSq));
    double res = (g_sumW - g_sumDW / maxd) / ((double)NN * (double)NN);
    out[0] = (float)res;
}

extern "C" void kernel_launch(void* const* d_in, const int* in_sizes, int n_in,
                              void* d_out, int out_size) {
    const float* emb = (const float*)d_in[0];   // [8192, 128] fp32
    const float* W   = (const float*)d_in[1];   // [8192, 8192] fp32
    float* out = (float*)d_out;

    cudaFuncSetAttribute(main_kernel, cudaFuncAttributeMaxDynamicSharedMemorySize,
                         SMEM_DYN);

    init_kernel<<<1, 1>>>();
    convert_kernel<<<(NN * DD) / 256, 256>>>(emb);
    norm_kernel<<<NN / 256, 256>>>(emb);
    main_kernel<<<NTRI, 256, SMEM_DYN>>>(W);
    finalize_kernel<<<1, 1>>>(out);
}